// round 8
// baseline (speedup 1.0000x reference)
#include <cuda_runtime.h>

// Problem dims (fixed per reference)
#define BB 4
#define TT 1024
#define SS 1024
#define CC 1024
#define HH 16
#define DD 64
#define BT (BB * TT)   // 4096

// Scratch buffers (allocation-free rule: __device__ globals)
__device__ float g_Q[BB * HH * TT * DD];     // [B,H,T,D]
__device__ float g_K[BB * HH * SS * DD];     // [B,H,S,D]
__device__ float g_V[BB * HH * SS * DD];     // [B,H,S,D]
__device__ float g_att[BB * TT * HH * DD];   // [B,T,H,D] == [4096, 1024]

// ---- packed f32x2 helpers (FFMA2 path; ptxas never emits from C++) --------
__device__ __forceinline__ unsigned long long splat2(float v) {
    unsigned long long r;
    asm("mov.b64 %0, {%1, %1};" : "=l"(r) : "r"(__float_as_uint(v)));
    return r;
}
__device__ __forceinline__ void fma2(unsigned long long& d,
                                     unsigned long long a, unsigned long long b) {
    asm("fma.rn.f32x2 %0, %1, %2, %3;" : "=l"(d) : "l"(a), "l"(b), "l"(d));
}
__device__ __forceinline__ void mul2(unsigned long long& d,
                                     unsigned long long a, unsigned long long b) {
    asm("mul.rn.f32x2 %0, %1, %2;" : "=l"(d) : "l"(a), "l"(b));
}
__device__ __forceinline__ float2 unpack2(unsigned long long p) {
    unsigned int lo, hi;
    asm("mov.b64 {%0, %1}, %2;" : "=r"(lo), "=r"(hi) : "l"(p));
    return make_float2(__uint_as_float(lo), __uint_as_float(hi));
}

// ---------------------------------------------------------------------------
// Fused QKV projection: Out[b,h,t,d] = sum_c X[b,t,c] * W[h,c,d]
// grid: (BT/128, HH/2, 3), block 256. Tile 128(m) x 128(n = 2 heads), BK=8.
// Double-buffered smem + register prefetch -> one sync per chunk.
// ---------------------------------------------------------------------------
__global__ __launch_bounds__(256, 2) void qkv_proj_kernel(
    const float* __restrict__ x,     // [BT, C]
    const float* __restrict__ y_enc, // [BT, C]
    const float* __restrict__ Wq, const float* __restrict__ Wk,
    const float* __restrict__ Wv,
    float* __restrict__ Qo, float* __restrict__ Ko, float* __restrict__ Vo)
{
    __shared__ float As[2][8][132];   // [buf][k][m]
    __shared__ float Bs[2][8][132];   // [buf][k][n]

    const int z = blockIdx.z;
    const float* X   = (z == 0) ? x  : y_enc;
    const float* W   = (z == 0) ? Wq : (z == 1) ? Wk : Wv;
    float*       Out = (z == 0) ? Qo : (z == 1) ? Ko : Vo;

    const int m0 = blockIdx.x * 128;
    const int h0 = blockIdx.y * 2;

    const int tid = threadIdx.x;
    const int tx = tid & 15;
    const int ty = tid >> 4;

    const int arow = tid >> 1;
    const int akq  = (tid & 1) * 4;
    const int bk = tid >> 5;
    const int bn = (tid & 31) * 4;
    const int bh = h0 + (bn >> 6);
    const int bd = bn & 63;

    const float* Xa = X + (size_t)(m0 + arow) * CC + akq;
    const float* Wb = W + ((size_t)bh * CC + bk) * DD + bd;

    unsigned long long acc2[8][4];
#pragma unroll
    for (int i = 0; i < 8; i++)
#pragma unroll
        for (int j = 0; j < 4; j++) acc2[i][j] = 0ull;

    float4 av = *reinterpret_cast<const float4*>(Xa);
    float4 bv = *reinterpret_cast<const float4*>(Wb);
    As[0][akq + 0][arow] = av.x;
    As[0][akq + 1][arow] = av.y;
    As[0][akq + 2][arow] = av.z;
    As[0][akq + 3][arow] = av.w;
    *reinterpret_cast<float4*>(&Bs[0][bk][bn]) = bv;
    __syncthreads();

    for (int it = 0; it < 128; it++) {
        if (it < 127) {
            av = *reinterpret_cast<const float4*>(Xa + (it + 1) * 8);
            bv = *reinterpret_cast<const float4*>(Wb + (size_t)(it + 1) * 8 * DD);
        }
        const float (*A)[132] = As[it & 1];
        const float (*B)[132] = Bs[it & 1];
#pragma unroll
        for (int kk = 0; kk < 8; kk++) {
            float4 a0 = *reinterpret_cast<const float4*>(&A[kk][ty * 8]);
            float4 a1 = *reinterpret_cast<const float4*>(&A[kk][ty * 8 + 4]);
            ulonglong2 bp0 = *reinterpret_cast<const ulonglong2*>(&B[kk][tx * 4]);
            ulonglong2 bp1 = *reinterpret_cast<const ulonglong2*>(&B[kk][64 + tx * 4]);
            unsigned long long bb2[4] = {bp0.x, bp0.y, bp1.x, bp1.y};
            float aa[8] = {a0.x, a0.y, a0.z, a0.w, a1.x, a1.y, a1.z, a1.w};
#pragma unroll
            for (int i = 0; i < 8; i++) {
                unsigned long long as = splat2(aa[i]);
#pragma unroll
                for (int j = 0; j < 4; j++) fma2(acc2[i][j], as, bb2[j]);
            }
        }
        if (it < 127) {
            const int nb = (it + 1) & 1;
            As[nb][akq + 0][arow] = av.x;
            As[nb][akq + 1][arow] = av.y;
            As[nb][akq + 2][arow] = av.z;
            As[nb][akq + 3][arow] = av.w;
            *reinterpret_cast<float4*>(&Bs[nb][bk][bn]) = bv;
            __syncthreads();
        }
    }

#pragma unroll
    for (int i = 0; i < 8; i++) {
        int m = m0 + ty * 8 + i;
        int b = m >> 10;
        int t = m & 1023;
        float2 p0 = unpack2(acc2[i][0]);
        float2 p1 = unpack2(acc2[i][1]);
        float2 p2 = unpack2(acc2[i][2]);
        float2 p3 = unpack2(acc2[i][3]);
        float* o0 = Out + (((size_t)(b * HH + h0)     * TT + t) * DD) + tx * 4;
        float* o1 = Out + (((size_t)(b * HH + h0 + 1) * TT + t) * DD) + tx * 4;
        *reinterpret_cast<float4*>(o0) = make_float4(p0.x, p0.y, p1.x, p1.y);
        *reinterpret_cast<float4*>(o1) = make_float4(p2.x, p2.y, p3.x, p3.y);
    }
}

// ---------------------------------------------------------------------------
// Flash attention: grid (T/128, B*H), block 256.
// Thread (tx = tid&7, ty = tid>>3): 4 query rows (4ty..) x 8 keys/dims (8tx..).
// Per-warp smem addresses dedup (q: 4 unique, k/v: 8 unique, P reads: bcast).
// ---------------------------------------------------------------------------
__global__ __launch_bounds__(256, 2) void attn_kernel(
    const float* __restrict__ Q, const float* __restrict__ K,
    const float* __restrict__ V, float* __restrict__ Oatt)
{
    extern __shared__ float sm[];
    float* Qt = sm;                  // [64 c][132 r]
    float* Kt = Qt + 64 * 132;       // [64 c][68 key]
    float* Vs = Kt + 64 * 68;        // [64 key][68 d]
    float* Ps = Vs + 64 * 68;        // [128 q][68 key]

    const int bh = blockIdx.y;
    const int q0 = blockIdx.x * 128;
    const float* Qb = Q + ((size_t)bh * TT + q0) * DD;
    const float* Kb = K + (size_t)bh * SS * DD;
    const float* Vb = V + (size_t)bh * SS * DD;

    const int tid = threadIdx.x;
    const int tx = tid & 7;          // key/dim group: 8tx..8tx+7
    const int ty = tid >> 3;         // row group: 4ty..4ty+3

    // load Q tile transposed: 128 rows x 64 c
#pragma unroll
    for (int p = 0; p < 8; p++) {
        int fq = tid + p * 256;
        int row = fq >> 4;
        int cq  = (fq & 15) * 4;
        float4 v = *reinterpret_cast<const float4*>(&Qb[(size_t)row * DD + cq]);
        Qt[(cq + 0) * 132 + row] = v.x;
        Qt[(cq + 1) * 132 + row] = v.y;
        Qt[(cq + 2) * 132 + row] = v.z;
        Qt[(cq + 3) * 132 + row] = v.w;
    }

    unsigned long long acc2[4][4];
#pragma unroll
    for (int i = 0; i < 4; i++)
#pragma unroll
        for (int j = 0; j < 4; j++) acc2[i][j] = 0ull;
    float mi[4], li[4];
#pragma unroll
    for (int i = 0; i < 4; i++) { mi[i] = -1e30f; li[i] = 0.f; }
    const float scale = 0.03125f;  // C^-0.5

    // prefetch K/V tile 0
    float4 kvr[4], vvr[4];
#pragma unroll
    for (int p = 0; p < 4; p++) {
        int fq = tid + p * 256;
        int key = fq >> 4;
        int cq  = (fq & 15) * 4;
        kvr[p] = *reinterpret_cast<const float4*>(&Kb[(size_t)key * DD + cq]);
        vvr[p] = *reinterpret_cast<const float4*>(&Vb[(size_t)key * DD + cq]);
    }

    for (int s0 = 0; s0 < SS; s0 += 64) {
        __syncthreads();
#pragma unroll
        for (int p = 0; p < 4; p++) {
            int fq = tid + p * 256;
            int key = fq >> 4;
            int cq  = (fq & 15) * 4;
            Kt[(cq + 0) * 68 + key] = kvr[p].x;
            Kt[(cq + 1) * 68 + key] = kvr[p].y;
            Kt[(cq + 2) * 68 + key] = kvr[p].z;
            Kt[(cq + 3) * 68 + key] = kvr[p].w;
            *reinterpret_cast<float4*>(&Vs[key * 68 + cq]) = vvr[p];
        }
        __syncthreads();

        if (s0 + 64 < SS) {
#pragma unroll
            for (int p = 0; p < 4; p++) {
                int fq = tid + p * 256;
                int key = (fq >> 4) + s0 + 64;
                int cq  = (fq & 15) * 4;
                kvr[p] = *reinterpret_cast<const float4*>(&Kb[(size_t)key * DD + cq]);
                vvr[p] = *reinterpret_cast<const float4*>(&Vb[(size_t)key * DD + cq]);
            }
        }

        // scores: rows 4ty+i (i<4), keys 8tx..8tx+7 (4 pairs)
        unsigned long long s2[4][4];
#pragma unroll
        for (int i = 0; i < 4; i++)
#pragma unroll
            for (int j = 0; j < 4; j++) s2[i][j] = 0ull;
#pragma unroll 8
        for (int c = 0; c < 64; c++) {
            ulonglong2 kp0 = *reinterpret_cast<const ulonglong2*>(&Kt[c * 68 + tx * 8]);
            ulonglong2 kp1 = *reinterpret_cast<const ulonglong2*>(&Kt[c * 68 + tx * 8 + 4]);
            float4 q4 = *reinterpret_cast<const float4*>(&Qt[c * 132 + ty * 4]);
            float qq[4] = {q4.x, q4.y, q4.z, q4.w};
#pragma unroll
            for (int i = 0; i < 4; i++) {
                unsigned long long qs = splat2(qq[i]);
                fma2(s2[i][0], qs, kp0.x);
                fma2(s2[i][1], qs, kp0.y);
                fma2(s2[i][2], qs, kp1.x);
                fma2(s2[i][3], qs, kp1.y);
            }
        }

        // online softmax; reduce across the 8 tx lanes (xor 1,2,4)
        const unsigned long long sc2 = splat2(scale);
#pragma unroll
        for (int i = 0; i < 4; i++) {
            mul2(s2[i][0], s2[i][0], sc2);
            mul2(s2[i][1], s2[i][1], sc2);
            mul2(s2[i][2], s2[i][2], sc2);
            mul2(s2[i][3], s2[i][3], sc2);
            float2 sa = unpack2(s2[i][0]);
            float2 sb = unpack2(s2[i][1]);
            float2 sc = unpack2(s2[i][2]);
            float2 sd = unpack2(s2[i][3]);
            float mx = fmaxf(fmaxf(fmaxf(sa.x, sa.y), fmaxf(sb.x, sb.y)),
                             fmaxf(fmaxf(sc.x, sc.y), fmaxf(sd.x, sd.y)));
            mx = fmaxf(mx, __shfl_xor_sync(0xffffffffu, mx, 1));
            mx = fmaxf(mx, __shfl_xor_sync(0xffffffffu, mx, 2));
            mx = fmaxf(mx, __shfl_xor_sync(0xffffffffu, mx, 4));
            float mn = fmaxf(mi[i], mx);
            float corr = __expf(mi[i] - mn);
            mi[i] = mn;
            float p0 = __expf(sa.x - mn);
            float p1 = __expf(sa.y - mn);
            float p2 = __expf(sb.x - mn);
            float p3 = __expf(sb.y - mn);
            float p4 = __expf(sc.x - mn);
            float p5 = __expf(sc.y - mn);
            float p6 = __expf(sd.x - mn);
            float p7 = __expf(sd.y - mn);
            float ps = ((p0 + p1) + (p2 + p3)) + ((p4 + p5) + (p6 + p7));
            ps += __shfl_xor_sync(0xffffffffu, ps, 1);
            ps += __shfl_xor_sync(0xffffffffu, ps, 2);
            ps += __shfl_xor_sync(0xffffffffu, ps, 4);
            li[i] = li[i] * corr + ps;
            unsigned long long cs = splat2(corr);
            mul2(acc2[i][0], acc2[i][0], cs);
            mul2(acc2[i][1], acc2[i][1], cs);
            mul2(acc2[i][2], acc2[i][2], cs);
            mul2(acc2[i][3], acc2[i][3], cs);
            float* pr = &Ps[(ty * 4 + i) * 68 + tx * 8];
            *reinterpret_cast<float4*>(pr)     = make_float4(p0, p1, p2, p3);
            *reinterpret_cast<float4*>(pr + 4) = make_float4(p4, p5, p6, p7);
        }
        __syncwarp();

        // PV: acc[i][pairs over dims 8tx..8tx+7] += P[row][key] * V[key][dim]
#pragma unroll 4
        for (int kg = 0; kg < 16; kg++) {
            const int key = kg * 4;
            ulonglong2 v0a = *reinterpret_cast<const ulonglong2*>(&Vs[(key + 0) * 68 + tx * 8]);
            ulonglong2 v0b = *reinterpret_cast<const ulonglong2*>(&Vs[(key + 0) * 68 + tx * 8 + 4]);
            ulonglong2 v1a = *reinterpret_cast<const ulonglong2*>(&Vs[(key + 1) * 68 + tx * 8]);
            ulonglong2 v1b = *reinterpret_cast<const ulonglong2*>(&Vs[(key + 1) * 68 + tx * 8 + 4]);
            ulonglong2 v2a = *reinterpret_cast<const ulonglong2*>(&Vs[(key + 2) * 68 + tx * 8]);
            ulonglong2 v2b = *reinterpret_cast<const ulonglong2*>(&Vs[(key + 2) * 68 + tx * 8 + 4]);
            ulonglong2 v3a = *reinterpret_cast<const ulonglong2*>(&Vs[(key + 3) * 68 + tx * 8]);
            ulonglong2 v3b = *reinterpret_cast<const ulonglong2*>(&Vs[(key + 3) * 68 + tx * 8 + 4]);
#pragma unroll
            for (int i = 0; i < 4; i++) {
                float4 p4 = *reinterpret_cast<const float4*>(&Ps[(ty * 4 + i) * 68 + key]);
                unsigned long long ps0 = splat2(p4.x);
                fma2(acc2[i][0], ps0, v0a.x);
                fma2(acc2[i][1], ps0, v0a.y);
                fma2(acc2[i][2], ps0, v0b.x);
                fma2(acc2[i][3], ps0, v0b.y);
                unsigned long long ps1 = splat2(p4.y);
                fma2(acc2[i][0], ps1, v1a.x);
                fma2(acc2[i][1], ps1, v1a.y);
                fma2(acc2[i][2], ps1, v1b.x);
                fma2(acc2[i][3], ps1, v1b.y);
                unsigned long long ps2 = splat2(p4.z);
                fma2(acc2[i][0], ps2, v2a.x);
                fma2(acc2[i][1], ps2, v2a.y);
                fma2(acc2[i][2], ps2, v2b.x);
                fma2(acc2[i][3], ps2, v2b.y);
                unsigned long long ps3 = splat2(p4.w);
                fma2(acc2[i][0], ps3, v3a.x);
                fma2(acc2[i][1], ps3, v3a.y);
                fma2(acc2[i][2], ps3, v3b.x);
                fma2(acc2[i][3], ps3, v3b.y);
            }
        }
        __syncwarp();
    }

    const int b  = bh >> 4;
    const int h_ = bh & 15;
#pragma unroll
    for (int i = 0; i < 4; i++) {
        int t = q0 + ty * 4 + i;
        float inv = 1.0f / li[i];
        float2 a0 = unpack2(acc2[i][0]);
        float2 a1 = unpack2(acc2[i][1]);
        float2 a2 = unpack2(acc2[i][2]);
        float2 a3 = unpack2(acc2[i][3]);
        float* op = Oatt + (((size_t)(b * TT + t) * HH + h_) * DD) + tx * 8;
        *reinterpret_cast<float4*>(op) =
            make_float4(a0.x * inv, a0.y * inv, a1.x * inv, a1.y * inv);
        *reinterpret_cast<float4*>(op + 4) =
            make_float4(a2.x * inv, a2.y * inv, a3.x * inv, a3.y * inv);
    }
}

// ---------------------------------------------------------------------------
// Output projection: Out[m,n] = sum_k A[m,k] * Wo[n,k] + bo[n]
// grid: (BT/128, C/128), block 256. Double-buffered BK=8.
// ---------------------------------------------------------------------------
__global__ __launch_bounds__(256, 2) void outproj_kernel(
    const float* __restrict__ A,    // [4096, 1024]
    const float* __restrict__ Wo,   // [C, C], used as Wo[n][k]
    const float* __restrict__ bo,   // [C]
    float* __restrict__ Out)        // [4096, 1024]
{
    __shared__ float As[2][8][132];
    __shared__ float Bs[2][8][132];

    const int m0 = blockIdx.x * 128;
    const int n0 = blockIdx.y * 128;
    const int tid = threadIdx.x;
    const int tx = tid & 15;
    const int ty = tid >> 4;

    const int arow = tid >> 1;
    const int akq  = (tid & 1) * 4;

    const float* Aa = A  + (size_t)(m0 + arow) * CC + akq;
    const float* Wb = Wo + (size_t)(n0 + arow) * CC + akq;

    unsigned long long acc2[8][4];
#pragma unroll
    for (int i = 0; i < 8; i++)
#pragma unroll
        for (int j = 0; j < 4; j++) acc2[i][j] = 0ull;

    float4 av = *reinterpret_cast<const float4*>(Aa);
    float4 bv = *reinterpret_cast<const float4*>(Wb);
    As[0][akq + 0][arow] = av.x;
    As[0][akq + 1][arow] = av.y;
    As[0][akq + 2][arow] = av.z;
    As[0][akq + 3][arow] = av.w;
    Bs[0][akq + 0][arow] = bv.x;
    Bs[0][akq + 1][arow] = bv.y;
    Bs[0][akq + 2][arow] = bv.z;
    Bs[0][akq + 3][arow] = bv.w;
    __syncthreads();

    for (int it = 0; it < 128; it++) {
        if (it < 127) {
            av = *reinterpret_cast<const float4*>(Aa + (it + 1) * 8);
            bv = *reinterpret_cast<const float4*>(Wb + (it + 1) * 8);
        }
        const float (*Ap)[132] = As[it & 1];
        const float (*Bp)[132] = Bs[it & 1];
#pragma unroll
        for (int kk = 0; kk < 8; kk++) {
            float4 a0 = *reinterpret_cast<const float4*>(&Ap[kk][ty * 8]);
            float4 a1 = *reinterpret_cast<const float4*>(&Ap[kk][ty * 8 + 4]);
            ulonglong2 bp0 = *reinterpret_cast<const ulonglong2*>(&Bp[kk][tx * 4]);
            ulonglong2 bp1 = *reinterpret_cast<const ulonglong2*>(&Bp[kk][64 + tx * 4]);
            unsigned long long bb2[4] = {bp0.x, bp0.y, bp1.x, bp1.y};
            float aa[8] = {a0.x, a0.y, a0.z, a0.w, a1.x, a1.y, a1.z, a1.w};
#pragma unroll
            for (int i = 0; i < 8; i++) {
                unsigned long long as = splat2(aa[i]);
#pragma unroll
                for (int j = 0; j < 4; j++) fma2(acc2[i][j], as, bb2[j]);
            }
        }
        if (it < 127) {
            const int nb = (it + 1) & 1;
            As[nb][akq + 0][arow] = av.x;
            As[nb][akq + 1][arow] = av.y;
            As[nb][akq + 2][arow] = av.z;
            As[nb][akq + 3][arow] = av.w;
            Bs[nb][akq + 0][arow] = bv.x;
            Bs[nb][akq + 1][arow] = bv.y;
            Bs[nb][akq + 2][arow] = bv.z;
            Bs[nb][akq + 3][arow] = bv.w;
            __syncthreads();
        }
    }

    float4 bias0 = *reinterpret_cast<const float4*>(&bo[n0 + tx * 4]);
    float4 bias1 = *reinterpret_cast<const float4*>(&bo[n0 + 64 + tx * 4]);
#pragma unroll
    for (int i = 0; i < 8; i++) {
        int m = m0 + ty * 8 + i;
        float2 p0 = unpack2(acc2[i][0]);
        float2 p1 = unpack2(acc2[i][1]);
        float2 p2 = unpack2(acc2[i][2]);
        float2 p3 = unpack2(acc2[i][3]);
        float* o0 = Out + (size_t)m * CC + n0 + tx * 4;
        float* o1 = Out + (size_t)m * CC + n0 + 64 + tx * 4;
        *reinterpret_cast<float4*>(o0) = make_float4(p0.x + bias0.x, p0.y + bias0.y,
                                                     p1.x + bias0.z, p1.y + bias0.w);
        *reinterpret_cast<float4*>(o1) = make_float4(p2.x + bias1.x, p2.y + bias1.y,
                                                     p3.x + bias1.z, p3.y + bias1.w);
    }
}

// ---------------------------------------------------------------------------
extern "C" void kernel_launch(void* const* d_in, const int* in_sizes, int n_in,
                              void* d_out, int out_size)
{
    const float* x     = (const float*)d_in[0];
    const float* y_enc = (const float*)d_in[1];
    const float* Wq    = (const float*)d_in[2];
    const float* Wk    = (const float*)d_in[3];
    const float* Wv    = (const float*)d_in[4];
    const float* Wo    = (const float*)d_in[5];
    const float* bo    = (const float*)d_in[6];
    float* out = (float*)d_out;

    float *pQ, *pK, *pV, *pA;
    cudaGetSymbolAddress((void**)&pQ, g_Q);
    cudaGetSymbolAddress((void**)&pK, g_K);
    cudaGetSymbolAddress((void**)&pV, g_V);
    cudaGetSymbolAddress((void**)&pA, g_att);

    const int attn_smem = (64 * 132 + 64 * 68 + 64 * 68 + 128 * 68) * (int)sizeof(float);
    cudaFuncSetAttribute(attn_kernel, cudaFuncAttributeMaxDynamicSharedMemorySize,
                         attn_smem);

    dim3 pg(BT / 128, HH / 2, 3);
    qkv_proj_kernel<<<pg, 256>>>(x, y_enc, Wq, Wk, Wv, pQ, pK, pV);

    dim3 ag(TT / 128, BB * HH);
    attn_kernel<<<ag, 256, attn_smem>>>(pQ, pK, pV, pA);

    dim3 og(BT / 128, CC / 128);
    outproj_kernel<<<og, 256>>>(pA, Wo, bo, out);
}

// round 9
// speedup vs baseline: 1.0003x; 1.0003x over previous
#include <cuda_runtime.h>

// Problem dims (fixed per reference)
#define BB 4
#define TT 1024
#define SS 1024
#define CC 1024
#define HH 16
#define DD 64
#define BT (BB * TT)   // 4096

// Scratch buffers (allocation-free rule: __device__ globals)
__device__ float g_Q[BB * HH * TT * DD];     // [B,H,T,D]
__device__ float g_K[BB * HH * SS * DD];     // [B,H,S,D]
__device__ float g_V[BB * HH * SS * DD];     // [B,H,S,D]
__device__ float g_att[BB * TT * HH * DD];   // [B,T,H,D] == [4096, 1024]

// ---- packed f32x2 helpers (FFMA2 path; ptxas never emits from C++) --------
__device__ __forceinline__ unsigned long long splat2(float v) {
    unsigned long long r;
    asm("mov.b64 %0, {%1, %1};" : "=l"(r) : "r"(__float_as_uint(v)));
    return r;
}
__device__ __forceinline__ void fma2(unsigned long long& d,
                                     unsigned long long a, unsigned long long b) {
    asm("fma.rn.f32x2 %0, %1, %2, %3;" : "=l"(d) : "l"(a), "l"(b), "l"(d));
}
__device__ __forceinline__ void mul2(unsigned long long& d,
                                     unsigned long long a, unsigned long long b) {
    asm("mul.rn.f32x2 %0, %1, %2;" : "=l"(d) : "l"(a), "l"(b));
}
__device__ __forceinline__ float2 unpack2(unsigned long long p) {
    unsigned int lo, hi;
    asm("mov.b64 {%0, %1}, %2;" : "=r"(lo), "=r"(hi) : "l"(p));
    return make_float2(__uint_as_float(lo), __uint_as_float(hi));
}

// ---------------------------------------------------------------------------
// Fused QKV projection: Out[b,h,t,d] = sum_c X[b,t,c] * W[h,c,d]
// grid: (BT/128, HH/2, 3), block 256. Tile 128(m) x 128(n = 2 heads), BK=8.
// Double-buffered smem + register prefetch -> one sync per chunk.
// ---------------------------------------------------------------------------
__global__ __launch_bounds__(256, 2) void qkv_proj_kernel(
    const float* __restrict__ x,     // [BT, C]
    const float* __restrict__ y_enc, // [BT, C]
    const float* __restrict__ Wq, const float* __restrict__ Wk,
    const float* __restrict__ Wv,
    float* __restrict__ Qo, float* __restrict__ Ko, float* __restrict__ Vo)
{
    __shared__ float As[2][8][132];   // [buf][k][m]
    __shared__ float Bs[2][8][132];   // [buf][k][n]

    const int z = blockIdx.z;
    const float* X   = (z == 0) ? x  : y_enc;
    const float* W   = (z == 0) ? Wq : (z == 1) ? Wk : Wv;
    float*       Out = (z == 0) ? Qo : (z == 1) ? Ko : Vo;

    const int m0 = blockIdx.x * 128;
    const int h0 = blockIdx.y * 2;

    const int tid = threadIdx.x;
    const int tx = tid & 15;
    const int ty = tid >> 4;

    const int arow = tid >> 1;
    const int akq  = (tid & 1) * 4;
    const int bk = tid >> 5;
    const int bn = (tid & 31) * 4;
    const int bh = h0 + (bn >> 6);
    const int bd = bn & 63;

    const float* Xa = X + (size_t)(m0 + arow) * CC + akq;
    const float* Wb = W + ((size_t)bh * CC + bk) * DD + bd;

    unsigned long long acc2[8][4];
#pragma unroll
    for (int i = 0; i < 8; i++)
#pragma unroll
        for (int j = 0; j < 4; j++) acc2[i][j] = 0ull;

    float4 av = *reinterpret_cast<const float4*>(Xa);
    float4 bv = *reinterpret_cast<const float4*>(Wb);
    As[0][akq + 0][arow] = av.x;
    As[0][akq + 1][arow] = av.y;
    As[0][akq + 2][arow] = av.z;
    As[0][akq + 3][arow] = av.w;
    *reinterpret_cast<float4*>(&Bs[0][bk][bn]) = bv;
    __syncthreads();

    for (int it = 0; it < 128; it++) {
        if (it < 127) {
            av = *reinterpret_cast<const float4*>(Xa + (it + 1) * 8);
            bv = *reinterpret_cast<const float4*>(Wb + (size_t)(it + 1) * 8 * DD);
        }
        const float (*A)[132] = As[it & 1];
        const float (*B)[132] = Bs[it & 1];
#pragma unroll
        for (int kk = 0; kk < 8; kk++) {
            float4 a0 = *reinterpret_cast<const float4*>(&A[kk][ty * 8]);
            float4 a1 = *reinterpret_cast<const float4*>(&A[kk][ty * 8 + 4]);
            ulonglong2 bp0 = *reinterpret_cast<const ulonglong2*>(&B[kk][tx * 4]);
            ulonglong2 bp1 = *reinterpret_cast<const ulonglong2*>(&B[kk][64 + tx * 4]);
            unsigned long long bb2[4] = {bp0.x, bp0.y, bp1.x, bp1.y};
            float aa[8] = {a0.x, a0.y, a0.z, a0.w, a1.x, a1.y, a1.z, a1.w};
#pragma unroll
            for (int i = 0; i < 8; i++) {
                unsigned long long as = splat2(aa[i]);
#pragma unroll
                for (int j = 0; j < 4; j++) fma2(acc2[i][j], as, bb2[j]);
            }
        }
        if (it < 127) {
            const int nb = (it + 1) & 1;
            As[nb][akq + 0][arow] = av.x;
            As[nb][akq + 1][arow] = av.y;
            As[nb][akq + 2][arow] = av.z;
            As[nb][akq + 3][arow] = av.w;
            *reinterpret_cast<float4*>(&Bs[nb][bk][bn]) = bv;
            __syncthreads();
        }
    }

#pragma unroll
    for (int i = 0; i < 8; i++) {
        int m = m0 + ty * 8 + i;
        int b = m >> 10;
        int t = m & 1023;
        float2 p0 = unpack2(acc2[i][0]);
        float2 p1 = unpack2(acc2[i][1]);
        float2 p2 = unpack2(acc2[i][2]);
        float2 p3 = unpack2(acc2[i][3]);
        float* o0 = Out + (((size_t)(b * HH + h0)     * TT + t) * DD) + tx * 4;
        float* o1 = Out + (((size_t)(b * HH + h0 + 1) * TT + t) * DD) + tx * 4;
        *reinterpret_cast<float4*>(o0) = make_float4(p0.x, p0.y, p1.x, p1.y);
        *reinterpret_cast<float4*>(o1) = make_float4(p2.x, p2.y, p3.x, p3.y);
    }
}

// ---------------------------------------------------------------------------
// Flash attention: grid (T/128, B*H), block 256.
// Thread (tx = tid&7, ty = tid>>3): 4 query rows (4ty..) x 8 keys/dims (8tx..).
// Per-warp smem addresses dedup (q: 4 unique, k/v: 8 unique, P reads: bcast).
// ---------------------------------------------------------------------------
__global__ __launch_bounds__(256, 2) void attn_kernel(
    const float* __restrict__ Q, const float* __restrict__ K,
    const float* __restrict__ V, float* __restrict__ Oatt)
{
    extern __shared__ float sm[];
    float* Qt = sm;                  // [64 c][132 r]
    float* Kt = Qt + 64 * 132;       // [64 c][68 key]
    float* Vs = Kt + 64 * 68;        // [64 key][68 d]
    float* Ps = Vs + 64 * 68;        // [128 q][68 key]

    const int bh = blockIdx.y;
    const int q0 = blockIdx.x * 128;
    const float* Qb = Q + ((size_t)bh * TT + q0) * DD;
    const float* Kb = K + (size_t)bh * SS * DD;
    const float* Vb = V + (size_t)bh * SS * DD;

    const int tid = threadIdx.x;
    const int tx = tid & 7;          // key/dim group: 8tx..8tx+7
    const int ty = tid >> 3;         // row group: 4ty..4ty+3

    // load Q tile transposed: 128 rows x 64 c
#pragma unroll
    for (int p = 0; p < 8; p++) {
        int fq = tid + p * 256;
        int row = fq >> 4;
        int cq  = (fq & 15) * 4;
        float4 v = *reinterpret_cast<const float4*>(&Qb[(size_t)row * DD + cq]);
        Qt[(cq + 0) * 132 + row] = v.x;
        Qt[(cq + 1) * 132 + row] = v.y;
        Qt[(cq + 2) * 132 + row] = v.z;
        Qt[(cq + 3) * 132 + row] = v.w;
    }

    unsigned long long acc2[4][4];
#pragma unroll
    for (int i = 0; i < 4; i++)
#pragma unroll
        for (int j = 0; j < 4; j++) acc2[i][j] = 0ull;
    float mi[4], li[4];
#pragma unroll
    for (int i = 0; i < 4; i++) { mi[i] = -1e30f; li[i] = 0.f; }
    const float scale = 0.03125f;  // C^-0.5

    // prefetch K/V tile 0
    float4 kvr[4], vvr[4];
#pragma unroll
    for (int p = 0; p < 4; p++) {
        int fq = tid + p * 256;
        int key = fq >> 4;
        int cq  = (fq & 15) * 4;
        kvr[p] = *reinterpret_cast<const float4*>(&Kb[(size_t)key * DD + cq]);
        vvr[p] = *reinterpret_cast<const float4*>(&Vb[(size_t)key * DD + cq]);
    }

    for (int s0 = 0; s0 < SS; s0 += 64) {
        __syncthreads();
#pragma unroll
        for (int p = 0; p < 4; p++) {
            int fq = tid + p * 256;
            int key = fq >> 4;
            int cq  = (fq & 15) * 4;
            Kt[(cq + 0) * 68 + key] = kvr[p].x;
            Kt[(cq + 1) * 68 + key] = kvr[p].y;
            Kt[(cq + 2) * 68 + key] = kvr[p].z;
            Kt[(cq + 3) * 68 + key] = kvr[p].w;
            *reinterpret_cast<float4*>(&Vs[key * 68 + cq]) = vvr[p];
        }
        __syncthreads();

        if (s0 + 64 < SS) {
#pragma unroll
            for (int p = 0; p < 4; p++) {
                int fq = tid + p * 256;
                int key = (fq >> 4) + s0 + 64;
                int cq  = (fq & 15) * 4;
                kvr[p] = *reinterpret_cast<const float4*>(&Kb[(size_t)key * DD + cq]);
                vvr[p] = *reinterpret_cast<const float4*>(&Vb[(size_t)key * DD + cq]);
            }
        }

        // scores: rows 4ty+i (i<4), keys 8tx..8tx+7 (4 pairs)
        unsigned long long s2[4][4];
#pragma unroll
        for (int i = 0; i < 4; i++)
#pragma unroll
            for (int j = 0; j < 4; j++) s2[i][j] = 0ull;
#pragma unroll 8
        for (int c = 0; c < 64; c++) {
            ulonglong2 kp0 = *reinterpret_cast<const ulonglong2*>(&Kt[c * 68 + tx * 8]);
            ulonglong2 kp1 = *reinterpret_cast<const ulonglong2*>(&Kt[c * 68 + tx * 8 + 4]);
            float4 q4 = *reinterpret_cast<const float4*>(&Qt[c * 132 + ty * 4]);
            float qq[4] = {q4.x, q4.y, q4.z, q4.w};
#pragma unroll
            for (int i = 0; i < 4; i++) {
                unsigned long long qs = splat2(qq[i]);
                fma2(s2[i][0], qs, kp0.x);
                fma2(s2[i][1], qs, kp0.y);
                fma2(s2[i][2], qs, kp1.x);
                fma2(s2[i][3], qs, kp1.y);
            }
        }

        // online softmax; reduce across the 8 tx lanes (xor 1,2,4)
        const unsigned long long sc2 = splat2(scale);
#pragma unroll
        for (int i = 0; i < 4; i++) {
            mul2(s2[i][0], s2[i][0], sc2);
            mul2(s2[i][1], s2[i][1], sc2);
            mul2(s2[i][2], s2[i][2], sc2);
            mul2(s2[i][3], s2[i][3], sc2);
            float2 sa = unpack2(s2[i][0]);
            float2 sb = unpack2(s2[i][1]);
            float2 sc = unpack2(s2[i][2]);
            float2 sd = unpack2(s2[i][3]);
            float mx = fmaxf(fmaxf(fmaxf(sa.x, sa.y), fmaxf(sb.x, sb.y)),
                             fmaxf(fmaxf(sc.x, sc.y), fmaxf(sd.x, sd.y)));
            mx = fmaxf(mx, __shfl_xor_sync(0xffffffffu, mx, 1));
            mx = fmaxf(mx, __shfl_xor_sync(0xffffffffu, mx, 2));
            mx = fmaxf(mx, __shfl_xor_sync(0xffffffffu, mx, 4));
            float mn = fmaxf(mi[i], mx);
            float corr = __expf(mi[i] - mn);
            mi[i] = mn;
            float p0 = __expf(sa.x - mn);
            float p1 = __expf(sa.y - mn);
            float p2 = __expf(sb.x - mn);
            float p3 = __expf(sb.y - mn);
            float p4 = __expf(sc.x - mn);
            float p5 = __expf(sc.y - mn);
            float p6 = __expf(sd.x - mn);
            float p7 = __expf(sd.y - mn);
            float ps = ((p0 + p1) + (p2 + p3)) + ((p4 + p5) + (p6 + p7));
            ps += __shfl_xor_sync(0xffffffffu, ps, 1);
            ps += __shfl_xor_sync(0xffffffffu, ps, 2);
            ps += __shfl_xor_sync(0xffffffffu, ps, 4);
            li[i] = li[i] * corr + ps;
            unsigned long long cs = splat2(corr);
            mul2(acc2[i][0], acc2[i][0], cs);
            mul2(acc2[i][1], acc2[i][1], cs);
            mul2(acc2[i][2], acc2[i][2], cs);
            mul2(acc2[i][3], acc2[i][3], cs);
            float* pr = &Ps[(ty * 4 + i) * 68 + tx * 8];
            *reinterpret_cast<float4*>(pr)     = make_float4(p0, p1, p2, p3);
            *reinterpret_cast<float4*>(pr + 4) = make_float4(p4, p5, p6, p7);
        }
        __syncwarp();

        // PV: acc[i][pairs over dims 8tx..8tx+7] += P[row][key] * V[key][dim]
#pragma unroll 4
        for (int kg = 0; kg < 16; kg++) {
            const int key = kg * 4;
            ulonglong2 v0a = *reinterpret_cast<const ulonglong2*>(&Vs[(key + 0) * 68 + tx * 8]);
            ulonglong2 v0b = *reinterpret_cast<const ulonglong2*>(&Vs[(key + 0) * 68 + tx * 8 + 4]);
            ulonglong2 v1a = *reinterpret_cast<const ulonglong2*>(&Vs[(key + 1) * 68 + tx * 8]);
            ulonglong2 v1b = *reinterpret_cast<const ulonglong2*>(&Vs[(key + 1) * 68 + tx * 8 + 4]);
            ulonglong2 v2a = *reinterpret_cast<const ulonglong2*>(&Vs[(key + 2) * 68 + tx * 8]);
            ulonglong2 v2b = *reinterpret_cast<const ulonglong2*>(&Vs[(key + 2) * 68 + tx * 8 + 4]);
            ulonglong2 v3a = *reinterpret_cast<const ulonglong2*>(&Vs[(key + 3) * 68 + tx * 8]);
            ulonglong2 v3b = *reinterpret_cast<const ulonglong2*>(&Vs[(key + 3) * 68 + tx * 8 + 4]);
#pragma unroll
            for (int i = 0; i < 4; i++) {
                float4 p4 = *reinterpret_cast<const float4*>(&Ps[(ty * 4 + i) * 68 + key]);
                unsigned long long ps0 = splat2(p4.x);
                fma2(acc2[i][0], ps0, v0a.x);
                fma2(acc2[i][1], ps0, v0a.y);
                fma2(acc2[i][2], ps0, v0b.x);
                fma2(acc2[i][3], ps0, v0b.y);
                unsigned long long ps1 = splat2(p4.y);
                fma2(acc2[i][0], ps1, v1a.x);
                fma2(acc2[i][1], ps1, v1a.y);
                fma2(acc2[i][2], ps1, v1b.x);
                fma2(acc2[i][3], ps1, v1b.y);
                unsigned long long ps2 = splat2(p4.z);
                fma2(acc2[i][0], ps2, v2a.x);
                fma2(acc2[i][1], ps2, v2a.y);
                fma2(acc2[i][2], ps2, v2b.x);
                fma2(acc2[i][3], ps2, v2b.y);
                unsigned long long ps3 = splat2(p4.w);
                fma2(acc2[i][0], ps3, v3a.x);
                fma2(acc2[i][1], ps3, v3a.y);
                fma2(acc2[i][2], ps3, v3b.x);
                fma2(acc2[i][3], ps3, v3b.y);
            }
        }
        __syncwarp();
    }

    const int b  = bh >> 4;
    const int h_ = bh & 15;
#pragma unroll
    for (int i = 0; i < 4; i++) {
        int t = q0 + ty * 4 + i;
        float inv = 1.0f / li[i];
        float2 a0 = unpack2(acc2[i][0]);
        float2 a1 = unpack2(acc2[i][1]);
        float2 a2 = unpack2(acc2[i][2]);
        float2 a3 = unpack2(acc2[i][3]);
        float* op = Oatt + (((size_t)(b * TT + t) * HH + h_) * DD) + tx * 8;
        *reinterpret_cast<float4*>(op) =
            make_float4(a0.x * inv, a0.y * inv, a1.x * inv, a1.y * inv);
        *reinterpret_cast<float4*>(op + 4) =
            make_float4(a2.x * inv, a2.y * inv, a3.x * inv, a3.y * inv);
    }
}

// ---------------------------------------------------------------------------
// Output projection: Out[m,n] = sum_k A[m,k] * Wo[n,k] + bo[n]
// grid: (BT/128, C/128), block 256. Double-buffered BK=8.
// ---------------------------------------------------------------------------
__global__ __launch_bounds__(256, 2) void outproj_kernel(
    const float* __restrict__ A,    // [4096, 1024]
    const float* __restrict__ Wo,   // [C, C], used as Wo[n][k]
    const float* __restrict__ bo,   // [C]
    float* __restrict__ Out)        // [4096, 1024]
{
    __shared__ float As[2][8][132];
    __shared__ float Bs[2][8][132];

    const int m0 = blockIdx.x * 128;
    const int n0 = blockIdx.y * 128;
    const int tid = threadIdx.x;
    const int tx = tid & 15;
    const int ty = tid >> 4;

    const int arow = tid >> 1;
    const int akq  = (tid & 1) * 4;

    const float* Aa = A  + (size_t)(m0 + arow) * CC + akq;
    const float* Wb = Wo + (size_t)(n0 + arow) * CC + akq;

    unsigned long long acc2[8][4];
#pragma unroll
    for (int i = 0; i < 8; i++)
#pragma unroll
        for (int j = 0; j < 4; j++) acc2[i][j] = 0ull;

    float4 av = *reinterpret_cast<const float4*>(Aa);
    float4 bv = *reinterpret_cast<const float4*>(Wb);
    As[0][akq + 0][arow] = av.x;
    As[0][akq + 1][arow] = av.y;
    As[0][akq + 2][arow] = av.z;
    As[0][akq + 3][arow] = av.w;
    Bs[0][akq + 0][arow] = bv.x;
    Bs[0][akq + 1][arow] = bv.y;
    Bs[0][akq + 2][arow] = bv.z;
    Bs[0][akq + 3][arow] = bv.w;
    __syncthreads();

    for (int it = 0; it < 128; it++) {
        if (it < 127) {
            av = *reinterpret_cast<const float4*>(Aa + (it + 1) * 8);
            bv = *reinterpret_cast<const float4*>(Wb + (it + 1) * 8);
        }
        const float (*Ap)[132] = As[it & 1];
        const float (*Bp)[132] = Bs[it & 1];
#pragma unroll
        for (int kk = 0; kk < 8; kk++) {
            float4 a0 = *reinterpret_cast<const float4*>(&Ap[kk][ty * 8]);
            float4 a1 = *reinterpret_cast<const float4*>(&Ap[kk][ty * 8 + 4]);
            ulonglong2 bp0 = *reinterpret_cast<const ulonglong2*>(&Bp[kk][tx * 4]);
            ulonglong2 bp1 = *reinterpret_cast<const ulonglong2*>(&Bp[kk][64 + tx * 4]);
            unsigned long long bb2[4] = {bp0.x, bp0.y, bp1.x, bp1.y};
            float aa[8] = {a0.x, a0.y, a0.z, a0.w, a1.x, a1.y, a1.z, a1.w};
#pragma unroll
            for (int i = 0; i < 8; i++) {
                unsigned long long as = splat2(aa[i]);
#pragma unroll
                for (int j = 0; j < 4; j++) fma2(acc2[i][j], as, bb2[j]);
            }
        }
        if (it < 127) {
            const int nb = (it + 1) & 1;
            As[nb][akq + 0][arow] = av.x;
            As[nb][akq + 1][arow] = av.y;
            As[nb][akq + 2][arow] = av.z;
            As[nb][akq + 3][arow] = av.w;
            Bs[nb][akq + 0][arow] = bv.x;
            Bs[nb][akq + 1][arow] = bv.y;
            Bs[nb][akq + 2][arow] = bv.z;
            Bs[nb][akq + 3][arow] = bv.w;
            __syncthreads();
        }
    }

    float4 bias0 = *reinterpret_cast<const float4*>(&bo[n0 + tx * 4]);
    float4 bias1 = *reinterpret_cast<const float4*>(&bo[n0 + 64 + tx * 4]);
#pragma unroll
    for (int i = 0; i < 8; i++) {
        int m = m0 + ty * 8 + i;
        float2 p0 = unpack2(acc2[i][0]);
        float2 p1 = unpack2(acc2[i][1]);
        float2 p2 = unpack2(acc2[i][2]);
        float2 p3 = unpack2(acc2[i][3]);
        float* o0 = Out + (size_t)m * CC + n0 + tx * 4;
        float* o1 = Out + (size_t)m * CC + n0 + 64 + tx * 4;
        *reinterpret_cast<float4*>(o0) = make_float4(p0.x + bias0.x, p0.y + bias0.y,
                                                     p1.x + bias0.z, p1.y + bias0.w);
        *reinterpret_cast<float4*>(o1) = make_float4(p2.x + bias1.x, p2.y + bias1.y,
                                                     p3.x + bias1.z, p3.y + bias1.w);
    }
}

// ---------------------------------------------------------------------------
extern "C" void kernel_launch(void* const* d_in, const int* in_sizes, int n_in,
                              void* d_out, int out_size)
{
    const float* x     = (const float*)d_in[0];
    const float* y_enc = (const float*)d_in[1];
    const float* Wq    = (const float*)d_in[2];
    const float* Wk    = (const float*)d_in[3];
    const float* Wv    = (const float*)d_in[4];
    const float* Wo    = (const float*)d_in[5];
    const float* bo    = (const float*)d_in[6];
    float* out = (float*)d_out;

    float *pQ, *pK, *pV, *pA;
    cudaGetSymbolAddress((void**)&pQ, g_Q);
    cudaGetSymbolAddress((void**)&pK, g_K);
    cudaGetSymbolAddress((void**)&pV, g_V);
    cudaGetSymbolAddress((void**)&pA, g_att);

    const int attn_smem = (64 * 132 + 64 * 68 + 64 * 68 + 128 * 68) * (int)sizeof(float);
    cudaFuncSetAttribute(attn_kernel, cudaFuncAttributeMaxDynamicSharedMemorySize,
                         attn_smem);

    dim3 pg(BT / 128, HH / 2, 3);
    qkv_proj_kernel<<<pg, 256>>>(x, y_enc, Wq, Wk, Wv, pQ, pK, pV);

    dim3 ag(TT / 128, BB * HH);
    attn_kernel<<<ag, 256, attn_smem>>>(pQ, pK, pV, pA);

    dim3 og(BT / 128, CC / 128);
    outproj_kernel<<<og, 256>>>(pA, Wo, bo, out);
}